// round 15
// baseline (speedup 1.0000x reference)
#include <cuda_runtime.h>
#include <cstdint>

// TVConv: per-pixel spatially-varying 3x3 depthwise conv, zero padding.
// x:           (B=8, C=96, H=128, W=128) fp32
// weight_maps: (1,   C=96, 3, 3, H, W)   fp32  (batch-invariant)
// out:         (B, C, H, W) fp32
//
// R14: cp.async pipeline. The occ-42% (needs <=64 regs) and prefetch
// (costs +12-16 regs) levers never coexisted because prefetched rows
// lived in registers. cp.async loads global->smem WITHOUT touching the
// register file: regs hold only weights(36) + one consuming row + accum.
// 3-stage thread-PRIVATE smem slots (no barriers; wait_group<2> orders a
// thread's own data; 3-stage distance makes refill safe). Halos via SHFL
// on post-LDS registers (R11: scalar gmem halos blow up L1). lb(256,4).

namespace {
constexpr int B = 8;
constexpr int C = 96;
constexpr int H = 128;
constexpr int W = 128;
constexpr int HW = H * W;
constexpr unsigned CHW = (unsigned)C * HW;
constexpr int THREADS = 256;
constexpr int NBLOCKS = C * H * (W / 4) / THREADS;  // 1536
constexpr int STAGES = 3;
}

__device__ __forceinline__ void cp_async16(uint32_t saddr, const float* gptr) {
    asm volatile("cp.async.ca.shared.global [%0], [%1], 16;"
                 :: "r"(saddr), "l"(gptr));
}
__device__ __forceinline__ void cp_commit() {
    asm volatile("cp.async.commit_group;");
}
template <int N>
__device__ __forceinline__ void cp_wait() {
    asm volatile("cp.async.wait_group %0;" :: "n"(N));
}

__global__ __launch_bounds__(THREADS, 4) void tvconv_kernel(
    const float* __restrict__ x,
    const float* __restrict__ wm,
    float* __restrict__ out)
{
    // [stage][row][tid] float4 slots; contiguous per warp -> conflict-free
    __shared__ float4 sx[STAGES][3][THREADS];   // 36 KB

    const int tid  = threadIdx.x;
    const int lane = tid & 31;                  // == w4 (W/4 == 32)
    int idx  = blockIdx.x * THREADS + tid;
    int t    = idx >> 5;
    int h    = t % H;
    int c    = t / H;
    int w0   = lane * 4;

    // ---- 9 weight taps, register-resident, streaming (read-once) ----
    const float* wbase = wm + (unsigned)c * 9u * HW + (unsigned)h * W + w0;
    float4 wt[9];
#pragma unroll
    for (int k = 0; k < 9; k++)
        wt[k] = __ldcs(reinterpret_cast<const float4*>(wbase + (unsigned)k * HW));

    const unsigned chw = (unsigned)c * HW + (unsigned)h * W + w0;
    const bool has_up = (h > 0), has_dn = (h < H - 1);

    // pre-zero pad-row slots (cp.async never writes them)
    const float4 z4 = make_float4(0.f, 0.f, 0.f, 0.f);
#pragma unroll
    for (int s = 0; s < STAGES; s++) {
        if (!has_up) sx[s][0][tid] = z4;
        if (!has_dn) sx[s][2][tid] = z4;
    }

    // smem byte addresses of this thread's 3 slots per stage
    uint32_t sbase = (uint32_t)__cvta_generic_to_shared(&sx[0][0][tid]);
    constexpr uint32_t ROWB = sizeof(float4) * THREADS;       // 4096
    constexpr uint32_t STGB = 3 * ROWB;                       // 12288

    // ---- prologue: issue batches 0..2 into stages 0..2 ----
#pragma unroll
    for (int s = 0; s < STAGES; s++) {
        const float* xb = x + (unsigned)s * CHW + chw;
        uint32_t sa = sbase + (uint32_t)s * STGB;
        cp_async16(sa + 1 * ROWB, xb);
        if (has_up) cp_async16(sa + 0 * ROWB, xb - W);
        if (has_dn) cp_async16(sa + 2 * ROWB, xb + W);
        cp_commit();
    }

#pragma unroll
    for (int b = 0; b < B; b++) {
        const int s = b % STAGES;
        cp_wait<2>();          // group b complete -> stage s holds batch b

        float a0 = 0.f, a1 = 0.f, a2 = 0.f, a3 = 0.f;
#pragma unroll
        for (int r = 0; r < 3; r++) {
            float4 v = sx[s][r][tid];
            float lf = __shfl_up_sync(0xffffffffu,  v.w, 1);
            float rt = __shfl_down_sync(0xffffffffu, v.x, 1);
            if (lane == 0)  lf = 0.f;   // w = -1  pad
            if (lane == 31) rt = 0.f;   // w = 128 pad
            float4 k0 = wt[3 * r + 0], k1 = wt[3 * r + 1], k2 = wt[3 * r + 2];
            a0 = fmaf(k0.x, lf,  fmaf(k1.x, v.x, fmaf(k2.x, v.y, a0)));
            a1 = fmaf(k0.y, v.x, fmaf(k1.y, v.y, fmaf(k2.y, v.z, a1)));
            a2 = fmaf(k0.z, v.y, fmaf(k1.z, v.z, fmaf(k2.z, v.w, a2)));
            a3 = fmaf(k0.w, v.z, fmaf(k1.w, v.w, fmaf(k2.w, rt,  a3)));
        }

        __stcs(reinterpret_cast<float4*>(out + (unsigned)b * CHW + chw),
               make_float4(a0, a1, a2, a3));

        // refill this stage with batch b+3 (provably safe at distance 3)
        if (b + STAGES < B) {
            const float* xn = x + (unsigned)(b + STAGES) * CHW + chw;
            uint32_t sa = sbase + (uint32_t)s * STGB;
            cp_async16(sa + 1 * ROWB, xn);
            if (has_up) cp_async16(sa + 0 * ROWB, xn - W);
            if (has_dn) cp_async16(sa + 2 * ROWB, xn + W);
        }
        cp_commit();           // unconditional: keeps group counting uniform
    }
}

extern "C" void kernel_launch(void* const* d_in, const int* in_sizes, int n_in,
                              void* d_out, int out_size)
{
    const float* x  = (const float*)d_in[0];
    const float* wm = (const float*)d_in[1];
    float* out      = (float*)d_out;

    tvconv_kernel<<<NBLOCKS, THREADS>>>(x, wm, out);
}

// round 17
// speedup vs baseline: 1.5811x; 1.5811x over previous
#include <cuda_runtime.h>
#include <cstdint>

// TVConv: per-pixel spatially-varying 3x3 depthwise conv, zero padding.
// x:           (B=8, C=96, H=128, W=128) fp32
// weight_maps: (1,   C=96, 3, 3, H, W)   fp32  (batch-invariant)
// out:         (B, C, H, W) fp32
//
// Structure is R7 (23.0us keeper): 4px/thread, warp==row, register
// weights, distance-1 prefetch, lb(256,3), SHFL halos.
// R15 = R7 with SWAPPED cache hints. Measured DRAM/replay was 114MB =
// wm 56 (streamed by __ldcs each replay!) + out 50 + x ~8 (x is L2-
// resident across graph replays). wm (56MB) fits L2 too — so retain the
// BIGGER read-once tensor instead: wm default-cached (L2-resident across
// replays), x __ldcs (evict-first, streamed 50MB/replay), out __stcs.
// Steady state: ~100MB/replay (-12%) and wm reads become L2 hits.

namespace {
constexpr int B = 8;
constexpr int C = 96;
constexpr int H = 128;
constexpr int W = 128;
constexpr int HW = H * W;
constexpr unsigned CHW = (unsigned)C * HW;
constexpr int THREADS = 256;
constexpr int NBLOCKS = C * H * (W / 4) / THREADS;  // 1536
}

__device__ __forceinline__ float4 ldg4_cs(const float* p) {
    return __ldcs(reinterpret_cast<const float4*>(p));
}

__device__ __forceinline__ void accum_row(
    float4 r, float4 k0, float4 k1, float4 k2,
    float& a0, float& a1, float& a2, float& a3, int lane)
{
    float left  = __shfl_up_sync(0xffffffffu,  r.w, 1);
    float right = __shfl_down_sync(0xffffffffu, r.x, 1);
    if (lane == 0)  left  = 0.f;   // w = -1  -> zero pad
    if (lane == 31) right = 0.f;   // w = 128 -> zero pad
    a0 = fmaf(k0.x, left, fmaf(k1.x, r.x, fmaf(k2.x, r.y, a0)));
    a1 = fmaf(k0.y, r.x,  fmaf(k1.y, r.y, fmaf(k2.y, r.z, a1)));
    a2 = fmaf(k0.z, r.y,  fmaf(k1.z, r.z, fmaf(k2.z, r.w, a2)));
    a3 = fmaf(k0.w, r.z,  fmaf(k1.w, r.w, fmaf(k2.w, right, a3)));
}

__global__ __launch_bounds__(THREADS, 3) void tvconv_kernel(
    const float* __restrict__ x,
    const float* __restrict__ wm,
    float* __restrict__ out)
{
    int idx  = blockIdx.x * THREADS + threadIdx.x;
    int lane = threadIdx.x & 31;       // == w4 (W/4 == 32)
    int t    = idx >> 5;
    int h    = t % H;
    int c    = t / H;
    int w0   = lane * 4;

    // ---- 9 weight taps, register-resident, DEFAULT cache policy:
    //      wm (56MB) fits L2 and stays resident across graph replays ----
    const float* wbase = wm + (unsigned)c * 9u * HW + (unsigned)h * W + w0;
    float4 wt[9];
#pragma unroll
    for (int k = 0; k < 9; k++)
        wt[k] = *reinterpret_cast<const float4*>(wbase + (unsigned)k * HW);

    const unsigned chw = (unsigned)c * HW + (unsigned)h * W + w0;
    const bool has_up = (h > 0), has_dn = (h < H - 1);
    const float4 z4 = make_float4(0.f, 0.f, 0.f, 0.f);

    // prime batch 0 (x = streaming/evict-first: read once per replay)
    const float* xp = x + chw;
    float4 c1 = ldg4_cs(xp);
    float4 c0 = has_up ? ldg4_cs(xp - W) : z4;
    float4 c2 = has_dn ? ldg4_cs(xp + W) : z4;

#pragma unroll
    for (int b = 0; b < B; b++) {
        float4 n0 = z4, n1 = z4, n2 = z4;
        if (b + 1 < B) {               // distance-1 prefetch of next batch
            const float* xn = x + (unsigned)(b + 1) * CHW + chw;
            n1 = ldg4_cs(xn);
            n0 = has_up ? ldg4_cs(xn - W) : z4;
            n2 = has_dn ? ldg4_cs(xn + W) : z4;
        }

        float a0 = 0.f, a1 = 0.f, a2 = 0.f, a3 = 0.f;
        accum_row(c0, wt[0], wt[1], wt[2], a0, a1, a2, a3, lane);
        accum_row(c1, wt[3], wt[4], wt[5], a0, a1, a2, a3, lane);
        accum_row(c2, wt[6], wt[7], wt[8], a0, a1, a2, a3, lane);

        __stcs(reinterpret_cast<float4*>(out + (unsigned)b * CHW + chw),
               make_float4(a0, a1, a2, a3));

        c0 = n0; c1 = n1; c2 = n2;
    }
}

extern "C" void kernel_launch(void* const* d_in, const int* in_sizes, int n_in,
                              void* d_out, int out_size)
{
    const float* x  = (const float*)d_in[0];
    const float* wm = (const float*)d_in[1];
    float* out      = (float*)d_out;

    tvconv_kernel<<<NBLOCKS, THREADS>>>(x, wm, out);
}